// round 11
// baseline (speedup 1.0000x reference)
#include <cuda_runtime.h>
#include <cuda_bf16.h>
#include <cuda_fp16.h>
#include <cstdint>

static constexpr int NNODES = 100000;
static constexpr int NEDGES = 3200000;
static constexpr int NFEAT  = 512;
static constexpr int NHID   = 256;
static constexpr int SCAN_B = 1024;
static constexpr int NBLK_SCAN = (NNODES + SCAN_B - 1) / SCAN_B;  // 98

// ---- static device scratch (allocation-free per harness rules) ----
__device__ __half         g_sup_h[NNODES * NHID];    // GEMM out fp16 (SpMM gathers)
__device__ __nv_bfloat16  g_xh[NNODES * NFEAT];      // x split hi
__device__ __nv_bfloat16  g_xl[NNODES * NFEAT];      // x split lo
__device__ __nv_bfloat16  g_h1h[NNODES * NHID];      // h1 split hi
__device__ __nv_bfloat16  g_h1l[NNODES * NHID];      // h1 split lo
__device__ __nv_bfloat16  g_w1hT[NHID * NFEAT];      // W1^T hi [N,K]
__device__ __nv_bfloat16  g_w1lT[NHID * NFEAT];
__device__ __nv_bfloat16  g_w2hT[NHID * NHID];       // W2^T hi [N,K]
__device__ __nv_bfloat16  g_w2lT[NHID * NHID];
__device__ int    g_rowptr[NNODES + 1];
__device__ int    g_cursor[NNODES];
__device__ int    g_deg[NNODES];
__device__ int    g_bsum[128];
__device__ int2   g_edge[NEDGES];                    // packed {col, val_bits}

// ============================ helpers ============================

__device__ __forceinline__ uint32_t smem_u32(const void* p) {
    uint32_t a;
    asm("{ .reg .u64 t; cvta.to.shared.u64 t, %1; cvt.u32.u64 %0, t; }"
        : "=r"(a) : "l"(p));
    return a;
}

// swizzle for 64-byte rows (8 rows x 64B atom)
__device__ __forceinline__ uint32_t sw64(uint32_t off) {
    return off ^ ((off >> 3) & 0x30);
}

__device__ __forceinline__ uint32_t pack_hi2(float a, float b, float& ra, float& rb) {
    __nv_bfloat16 ha = __float2bfloat16(a);
    __nv_bfloat16 hb = __float2bfloat16(b);
    ra = a - __bfloat162float(ha);
    rb = b - __bfloat162float(hb);
    __nv_bfloat162 t; t.x = ha; t.y = hb;
    return *reinterpret_cast<uint32_t*>(&t);
}

__device__ __forceinline__ uint32_t pack_bf16x2(float a, float b) {
    __nv_bfloat162 t;
    t.x = __float2bfloat16(a);
    t.y = __float2bfloat16(b);
    return *reinterpret_cast<uint32_t*>(&t);
}

__device__ __forceinline__ void ldsm_x4(uint32_t* r, uint32_t addr) {
    asm volatile("ldmatrix.sync.aligned.m8n8.x4.shared.b16 {%0,%1,%2,%3}, [%4];"
        : "=r"(r[0]), "=r"(r[1]), "=r"(r[2]), "=r"(r[3]) : "r"(addr));
}

__device__ __forceinline__ void mma_bf16(float* c, const uint32_t* a,
                                         uint32_t b0, uint32_t b1) {
    asm volatile(
        "mma.sync.aligned.m16n8k16.row.col.f32.bf16.bf16.f32 "
        "{%0,%1,%2,%3}, {%4,%5,%6,%7}, {%8,%9}, {%0,%1,%2,%3};"
        : "+f"(c[0]), "+f"(c[1]), "+f"(c[2]), "+f"(c[3])
        : "r"(a[0]), "r"(a[1]), "r"(a[2]), "r"(a[3]), "r"(b0), "r"(b1));
}

__device__ __forceinline__ void cp_async16(uint32_t smem_addr, const void* gmem) {
    asm volatile("cp.async.ca.shared.global [%0], [%1], 16;"
        :: "r"(smem_addr), "l"(gmem));
}
__device__ __forceinline__ void cp_commit() {
    asm volatile("cp.async.commit_group;");
}
template<int N>
__device__ __forceinline__ void cp_wait() {
    asm volatile("cp.async.wait_group %0;" :: "n"(N));
}

// ============================ CSR construction ============================

__global__ void zero_deg_kernel() {
    int i = blockIdx.x * blockDim.x + threadIdx.x;
    if (i < NNODES) g_deg[i] = 0;
}

__global__ void count_deg_kernel(const int* __restrict__ erow) {
    int e = blockIdx.x * blockDim.x + threadIdx.x;
    if (e < NEDGES) atomicAdd(&g_deg[erow[e]], 1);
}

__global__ void scan1_kernel() {
    __shared__ int s[SCAN_B];
    int tx = threadIdx.x;
    int gid = blockIdx.x * SCAN_B + tx;
    int v = (gid < NNODES) ? g_deg[gid] : 0;
    s[tx] = v;
    __syncthreads();
    for (int off = 1; off < SCAN_B; off <<= 1) {
        int t = (tx >= off) ? s[tx - off] : 0;
        __syncthreads();
        s[tx] += t;
        __syncthreads();
    }
    if (gid < NNODES) g_rowptr[gid + 1] = s[tx];
    if (tx == SCAN_B - 1) g_bsum[blockIdx.x] = s[tx];
}

__global__ void scan2_kernel() {
    __shared__ int s[128];
    int tx = threadIdx.x;
    int v = (tx < NBLK_SCAN) ? g_bsum[tx] : 0;
    s[tx] = v;
    __syncthreads();
    for (int off = 1; off < 128; off <<= 1) {
        int t = (tx >= off) ? s[tx - off] : 0;
        __syncthreads();
        s[tx] += t;
        __syncthreads();
    }
    if (tx < NBLK_SCAN) g_bsum[tx] = s[tx];
}

__global__ void scan3_kernel() {
    int gid = blockIdx.x * SCAN_B + threadIdx.x;
    if (gid < NNODES) {
        int off = blockIdx.x ? g_bsum[blockIdx.x - 1] : 0;
        int v = g_rowptr[gid + 1] + off;
        g_rowptr[gid + 1] = v;
        if (gid + 1 < NNODES) g_cursor[gid + 1] = v;
        if (gid == 0) { g_rowptr[0] = 0; g_cursor[0] = 0; }
    }
}

__global__ void scatter_kernel(const int* __restrict__ erow,
                               const int* __restrict__ ecol,
                               const float* __restrict__ eval) {
    int e = blockIdx.x * blockDim.x + threadIdx.x;
    if (e < NEDGES) {
        int r = erow[e];
        int p = atomicAdd(&g_cursor[r], 1);
        g_edge[p] = make_int2(ecol[e], __float_as_int(eval[e]));
    }
}

// ============================ operand splitting ============================

// X [n] fp32 -> Xh/Xl bf16 (same layout), vectorized by 4
__global__ void split_x_kernel(const float4* __restrict__ X,
                               uint2* __restrict__ Xh, uint2* __restrict__ Xl, int n4) {
    int i = blockIdx.x * blockDim.x + threadIdx.x;
    if (i >= n4) return;
    float4 v = X[i];
    float rx, ry, rz, rw;
    uint32_t h0 = pack_hi2(v.x, v.y, rx, ry);
    uint32_t h1 = pack_hi2(v.z, v.w, rz, rw);
    Xh[i] = make_uint2(h0, h1);
    Xl[i] = make_uint2(pack_bf16x2(rx, ry), pack_bf16x2(rz, rw));
}

// W [K, N] fp32 -> WhT/WlT [N, K] bf16
__global__ void split_w_kernel(const float* __restrict__ W, int K, int Nn,
                               __nv_bfloat16* __restrict__ WhT,
                               __nv_bfloat16* __restrict__ WlT) {
    int idx = blockIdx.x * blockDim.x + threadIdx.x;
    if (idx >= K * Nn) return;
    int k = idx / Nn, n = idx % Nn;
    float x = W[idx];
    __nv_bfloat16 h = __float2bfloat16(x);
    WhT[(size_t)n * K + k] = h;
    WlT[(size_t)n * K + k] = __float2bfloat16(x - __bfloat162float(h));
}

// ============================ bf16-split tensor-core GEMM ============================
// Ch[M,Nn] = fp16( A[M,K] @ B[K,Nn] ), C ~= Ah*Bh + Ah*Bl + Al*Bh (fp32 acc).
// All operands pre-split bf16: A [M,K] hi/lo, B^T [Nn,K] hi/lo.
// Block tile 128x128, BK=32, 256 threads, 8 warps (each 32x64, B streamed).
// 3-stage cp.async pipeline, one __syncthreads per chunk, 2 CTAs/SM.

static constexpr int ST_AH = 0;
static constexpr int ST_AL = 8192;
static constexpr int ST_BH = 16384;
static constexpr int ST_BL = 24576;
static constexpr int STAGE_BYTES = 32768;
static constexpr int NSTAGES = 3;
static constexpr int GEMM_SMEM = NSTAGES * STAGE_BYTES;   // 98304

__global__ __launch_bounds__(256, 2) void gemm_split_kernel(
    int M, int Nn, int K,
    const __nv_bfloat16* __restrict__ Ah, const __nv_bfloat16* __restrict__ Al,
    const __nv_bfloat16* __restrict__ BhT, const __nv_bfloat16* __restrict__ BlT,
    __half* __restrict__ Ch)
{
    extern __shared__ char smem[];
    uint32_t sb = smem_u32(smem);

    int tid = threadIdx.x;
    int lane = tid & 31;
    int wid = tid >> 5;
    int wm = wid & 3;          // 4 x 32 rows
    int wn = wid >> 2;         // 2 x 64 cols
    int m0 = blockIdx.y * 128;
    int n0 = blockIdx.x * 128;

    // ---- staging coords: thread covers row (tid&127), 32B half (tid>>7) ----
    int srow = tid & 127;
    int shalf = tid >> 7;                       // 0/1 -> bytes [half*32, +32)
    int ar = m0 + srow;
    size_t asrc = (size_t)((ar < M) ? ar : 0) * K + shalf * 16;   // elements
    size_t bsrc = (size_t)(n0 + srow) * K + shalf * 16;
    uint32_t d0 = sw64((uint32_t)(srow * 64 + shalf * 32));
    uint32_t d1 = sw64((uint32_t)(srow * 64 + shalf * 32 + 16));

    float acc[2][8][4];
#pragma unroll
    for (int i = 0; i < 2; i++)
#pragma unroll
        for (int j = 0; j < 8; j++)
#pragma unroll
            for (int q = 0; q < 4; q++) acc[i][j][q] = 0.f;

    const int NC = K / 32;

    auto stage = [&](int ch, int buf) {
        int k0 = ch * 32;
        uint32_t st = sb + buf * STAGE_BYTES;
        cp_async16(st + ST_AH + d0, Ah + asrc + k0);
        cp_async16(st + ST_AH + d1, Ah + asrc + k0 + 8);
        cp_async16(st + ST_AL + d0, Al + asrc + k0);
        cp_async16(st + ST_AL + d1, Al + asrc + k0 + 8);
        cp_async16(st + ST_BH + d0, BhT + bsrc + k0);
        cp_async16(st + ST_BH + d1, BhT + bsrc + k0 + 8);
        cp_async16(st + ST_BL + d0, BlT + bsrc + k0);
        cp_async16(st + ST_BL + d1, BlT + bsrc + k0 + 8);
    };

    auto compute = [&](int buf) {
        uint32_t st = sb + buf * STAGE_BYTES;
        // A fragments cached: [s][mt]
        uint32_t ah[2][2][4], al[2][2][4];
#pragma unroll
        for (int s = 0; s < 2; s++) {
            uint32_t roff = (uint32_t)((wm * 32 + (lane & 15)) * 64
                                       + s * 32 + (lane >> 4) * 16);
#pragma unroll
            for (int mt = 0; mt < 2; mt++) {
                uint32_t off = roff + (uint32_t)(mt * 16 * 64);
                ldsm_x4(ah[s][mt], st + ST_AH + sw64(off));
                ldsm_x4(al[s][mt], st + ST_AL + sw64(off));
            }
        }
        // B streamed per n-tile (8 tiles of n=8)
        uint32_t bro = (uint32_t)((wn * 64 + (lane & 7)) * 64 + (lane >> 3) * 16);
#pragma unroll
        for (int nt = 0; nt < 8; nt++) {
            uint32_t off = bro + (uint32_t)(nt * 8 * 64);
            uint32_t bh[4], bl[4];
            ldsm_x4(bh, st + ST_BH + sw64(off));
            ldsm_x4(bl, st + ST_BL + sw64(off));
#pragma unroll
            for (int s = 0; s < 2; s++)
#pragma unroll
                for (int mt = 0; mt < 2; mt++) {
                    mma_bf16(acc[mt][nt], ah[s][mt], bh[2 * s], bh[2 * s + 1]);
                    mma_bf16(acc[mt][nt], ah[s][mt], bl[2 * s], bl[2 * s + 1]);
                    mma_bf16(acc[mt][nt], al[s][mt], bh[2 * s], bh[2 * s + 1]);
                }
        }
    };

    // ---- 3-stage pipeline ----
    stage(0, 0); cp_commit();
    stage(1, 1); cp_commit();

    for (int ch = 0; ch < NC; ch++) {
        if (ch == NC - 1) cp_wait<0>(); else cp_wait<1>();
        __syncthreads();
        compute(ch % NSTAGES);
        if (ch + 2 < NC) {
            stage(ch + 2, (ch + 2) % NSTAGES);
            cp_commit();
        }
    }

    // ---- epilogue: fp32 acc -> fp16 ----
#pragma unroll
    for (int mt = 0; mt < 2; mt++) {
        int r0 = m0 + wm * 32 + mt * 16 + (lane >> 2);
        int r1 = r0 + 8;
#pragma unroll
        for (int nt = 0; nt < 8; nt++) {
            int c = n0 + wn * 64 + nt * 8 + (lane & 3) * 2;
            if (r0 < M)
                *reinterpret_cast<__half2*>(Ch + (size_t)r0 * Nn + c) =
                    __floats2half2_rn(acc[mt][nt][0], acc[mt][nt][1]);
            if (r1 < M)
                *reinterpret_cast<__half2*>(Ch + (size_t)r1 * Nn + c) =
                    __floats2half2_rn(acc[mt][nt][2], acc[mt][nt][3]);
        }
    }
}

// ============================ SpMM (fp16 gather) + bias + PReLU ============================
// Warp per row: 32 lanes x 8 fp16 features (16B) = 256 features.
// SPLIT_OUT=true: write bf16 hi/lo (feeds GEMM2). false: write fp32 (final out).

template<bool SPLIT_OUT>
__global__ __launch_bounds__(256) void spmm_bias_prelu_kernel(
    const uint4* __restrict__ sup, const float* __restrict__ bias,
    const float* __restrict__ alpha, float4* __restrict__ outF,
    uint4* __restrict__ outH, uint4* __restrict__ outL)
{
    int lane = threadIdx.x & 31;
    int wrp  = threadIdx.x >> 5;
    int r = blockIdx.x * 8 + wrp;
    if (r >= NNODES) return;

    int s = g_rowptr[r];
    int e = g_rowptr[r + 1];

    float acc[8];
#pragma unroll
    for (int q = 0; q < 8; q++) acc[q] = 0.f;

    int j = s;
    for (; j + 1 < e; j += 2) {
        int2 E0 = g_edge[j];
        int2 E1 = g_edge[j + 1];
        float v0 = __int_as_float(E0.y);
        float v1 = __int_as_float(E1.y);
        uint4 p0 = sup[(size_t)E0.x * 32 + lane];
        uint4 p1 = sup[(size_t)E1.x * 32 + lane];
        const uint32_t* w0 = &p0.x;
        const uint32_t* w1 = &p1.x;
#pragma unroll
        for (int q = 0; q < 4; q++) {
            float2 f0 = __half22float2(*reinterpret_cast<const __half2*>(&w0[q]));
            float2 f1 = __half22float2(*reinterpret_cast<const __half2*>(&w1[q]));
            acc[2 * q + 0] += v0 * f0.x + v1 * f1.x;
            acc[2 * q + 1] += v0 * f0.y + v1 * f1.y;
        }
    }
    if (j < e) {
        int2 E0 = g_edge[j];
        float v0 = __int_as_float(E0.y);
        uint4 p0 = sup[(size_t)E0.x * 32 + lane];
        const uint32_t* w0 = &p0.x;
#pragma unroll
        for (int q = 0; q < 4; q++) {
            float2 f0 = __half22float2(*reinterpret_cast<const __half2*>(&w0[q]));
            acc[2 * q + 0] += v0 * f0.x;
            acc[2 * q + 1] += v0 * f0.y;
        }
    }

    float a = alpha[0];
    const float4* bp = reinterpret_cast<const float4*>(bias) + lane * 2;
    float4 b0 = bp[0], b1 = bp[1];
    float o[8];
    o[0] = acc[0] + b0.x; o[1] = acc[1] + b0.y;
    o[2] = acc[2] + b0.z; o[3] = acc[3] + b0.w;
    o[4] = acc[4] + b1.x; o[5] = acc[5] + b1.y;
    o[6] = acc[6] + b1.z; o[7] = acc[7] + b1.w;
#pragma unroll
    for (int q = 0; q < 8; q++) o[q] = o[q] >= 0.f ? o[q] : a * o[q];

    if (SPLIT_OUT) {
        float rr[8];
        uint4 hv, lv;
        hv.x = pack_hi2(o[0], o[1], rr[0], rr[1]);
        hv.y = pack_hi2(o[2], o[3], rr[2], rr[3]);
        hv.z = pack_hi2(o[4], o[5], rr[4], rr[5]);
        hv.w = pack_hi2(o[6], o[7], rr[6], rr[7]);
        lv.x = pack_bf16x2(rr[0], rr[1]);
        lv.y = pack_bf16x2(rr[2], rr[3]);
        lv.z = pack_bf16x2(rr[4], rr[5]);
        lv.w = pack_bf16x2(rr[6], rr[7]);
        outH[(size_t)r * 32 + lane] = hv;
        outL[(size_t)r * 32 + lane] = lv;
    } else {
        float4* op = outF + (size_t)r * 64 + lane * 2;
        op[0] = make_float4(o[0], o[1], o[2], o[3]);
        op[1] = make_float4(o[4], o[5], o[6], o[7]);
    }
}

// ============================ launch ============================

extern "C" void kernel_launch(void* const* d_in, const int* in_sizes, int n_in,
                              void* d_out, int out_size) {
    const float* x     = (const float*)d_in[0];
    const int*   erow  = (const int*)  d_in[1];
    const int*   ecol  = (const int*)  d_in[2];
    const float* eval  = (const float*)d_in[3];
    const float* W1    = (const float*)d_in[4];
    const float* b1    = (const float*)d_in[5];
    const float* W2    = (const float*)d_in[6];
    const float* b2    = (const float*)d_in[7];
    const float* alpha = (const float*)d_in[8];
    float* out = (float*)d_out;

    __half* suph = nullptr;
    __nv_bfloat16 *xh = nullptr, *xl = nullptr, *h1h = nullptr, *h1l = nullptr;
    __nv_bfloat16 *w1hT = nullptr, *w1lT = nullptr, *w2hT = nullptr, *w2lT = nullptr;
    cudaGetSymbolAddress((void**)&suph, g_sup_h);
    cudaGetSymbolAddress((void**)&xh, g_xh);
    cudaGetSymbolAddress((void**)&xl, g_xl);
    cudaGetSymbolAddress((void**)&h1h, g_h1h);
    cudaGetSymbolAddress((void**)&h1l, g_h1l);
    cudaGetSymbolAddress((void**)&w1hT, g_w1hT);
    cudaGetSymbolAddress((void**)&w1lT, g_w1lT);
    cudaGetSymbolAddress((void**)&w2hT, g_w2hT);
    cudaGetSymbolAddress((void**)&w2lT, g_w2lT);

    cudaFuncSetAttribute(gemm_split_kernel,
                         cudaFuncAttributeMaxDynamicSharedMemorySize, GEMM_SMEM);

    dim3 gemm_grid(NHID / 128, (NNODES + 127) / 128);   // x = n (fastest) -> A L2 reuse
    int spmm_grid = (NNODES + 7) / 8;
    int n4 = NNODES * NFEAT / 4;

    split_w_kernel<<<(NFEAT * NHID + 255) / 256, 256>>>(W1, NFEAT, NHID, w1hT, w1lT);   // 0
    split_w_kernel<<<(NHID * NHID + 255) / 256, 256>>>(W2, NHID, NHID, w2hT, w2lT);     // 1
    split_x_kernel<<<(n4 + 255) / 256, 256>>>((const float4*)x, (uint2*)xh, (uint2*)xl, n4); // 2
    gemm_split_kernel<<<gemm_grid, 256, GEMM_SMEM>>>(
        NNODES, NHID, NFEAT, xh, xl, w1hT, w1lT, suph);                                 // 3 (captured)
    zero_deg_kernel<<<(NNODES + 255) / 256, 256>>>();                                   // 4
    count_deg_kernel<<<NEDGES / 256, 256>>>(erow);                                      // 5
    scan1_kernel<<<NBLK_SCAN, SCAN_B>>>();                                              // 6
    scan2_kernel<<<1, 128>>>();                                                         // 7
    scan3_kernel<<<NBLK_SCAN, SCAN_B>>>();                                              // 8
    scatter_kernel<<<NEDGES / 256, 256>>>(erow, ecol, eval);                            // 9
    spmm_bias_prelu_kernel<true><<<spmm_grid, 256>>>(
        (const uint4*)suph, b1, alpha, nullptr, (uint4*)h1h, (uint4*)h1l);              // 10
    gemm_split_kernel<<<gemm_grid, 256, GEMM_SMEM>>>(
        NNODES, NHID, NHID, h1h, h1l, w2hT, w2lT, suph);                                // 11
    spmm_bias_prelu_kernel<false><<<spmm_grid, 256>>>(
        (const uint4*)suph, b2, alpha, (float4*)out, nullptr, nullptr);                 // 12
}

// round 15
// speedup vs baseline: 1.4305x; 1.4305x over previous
#include <cuda_runtime.h>
#include <cuda_fp16.h>
#include <cstdint>

static constexpr int NNODES = 100000;
static constexpr int NEDGES = 3200000;
static constexpr int NFEAT  = 512;
static constexpr int NHID   = 256;
static constexpr int SCAN_B = 1024;
static constexpr int NBLK_SCAN = (NNODES + SCAN_B - 1) / SCAN_B;  // 98

// ---- static device scratch (allocation-free per harness rules) ----
__device__ __half g_sup_h[NNODES * NHID];   // GEMM out fp16 (SpMM gathers)
__device__ __half g_x_h[NNODES * NFEAT];    // x in fp16
__device__ __half g_h1_h[NNODES * NHID];    // layer-1 out fp16 (feeds GEMM2)
__device__ __half g_w1T[NHID * NFEAT];      // W1^T fp16 [N,K]
__device__ __half g_w2T[NHID * NHID];       // W2^T fp16 [N,K]
__device__ int    g_rowptr[NNODES + 1];
__device__ int    g_cursor[NNODES];
__device__ int    g_deg[NNODES];
__device__ int    g_bsum[128];
__device__ int2   g_edge[NEDGES];           // packed {col, val_bits}

// ============================ helpers ============================

__device__ __forceinline__ uint32_t smem_u32(const void* p) {
    uint32_t a;
    asm("{ .reg .u64 t; cvta.to.shared.u64 t, %1; cvt.u32.u64 %0, t; }"
        : "=r"(a) : "l"(p));
    return a;
}

// swizzle for 64-byte rows (8 rows x 64B atom)
__device__ __forceinline__ uint32_t sw64(uint32_t off) {
    return off ^ ((off >> 3) & 0x30);
}

__device__ __forceinline__ uint32_t h2_bits(__half2 h) {
    return *reinterpret_cast<uint32_t*>(&h);
}

__device__ __forceinline__ void ldsm_x4(uint32_t* r, uint32_t addr) {
    asm volatile("ldmatrix.sync.aligned.m8n8.x4.shared.b16 {%0,%1,%2,%3}, [%4];"
        : "=r"(r[0]), "=r"(r[1]), "=r"(r[2]), "=r"(r[3]) : "r"(addr));
}

__device__ __forceinline__ void mma_f16(float* c, const uint32_t* a,
                                        uint32_t b0, uint32_t b1) {
    asm volatile(
        "mma.sync.aligned.m16n8k16.row.col.f32.f16.f16.f32 "
        "{%0,%1,%2,%3}, {%4,%5,%6,%7}, {%8,%9}, {%0,%1,%2,%3};"
        : "+f"(c[0]), "+f"(c[1]), "+f"(c[2]), "+f"(c[3])
        : "r"(a[0]), "r"(a[1]), "r"(a[2]), "r"(a[3]), "r"(b0), "r"(b1));
}

__device__ __forceinline__ void cp_async16(uint32_t smem_addr, const void* gmem) {
    asm volatile("cp.async.ca.shared.global [%0], [%1], 16;"
        :: "r"(smem_addr), "l"(gmem));
}
__device__ __forceinline__ void cp_commit() {
    asm volatile("cp.async.commit_group;");
}
template<int N>
__device__ __forceinline__ void cp_wait() {
    asm volatile("cp.async.wait_group %0;" :: "n"(N));
}

// ============================ CSR construction ============================

__global__ void zero_deg_kernel() {
    int i = blockIdx.x * blockDim.x + threadIdx.x;
    if (i < NNODES) g_deg[i] = 0;
}

__global__ void count_deg_kernel(const int* __restrict__ erow) {
    int e = blockIdx.x * blockDim.x + threadIdx.x;
    if (e < NEDGES) atomicAdd(&g_deg[erow[e]], 1);
}

__global__ void scan1_kernel() {
    __shared__ int s[SCAN_B];
    int tx = threadIdx.x;
    int gid = blockIdx.x * SCAN_B + tx;
    int v = (gid < NNODES) ? g_deg[gid] : 0;
    s[tx] = v;
    __syncthreads();
    for (int off = 1; off < SCAN_B; off <<= 1) {
        int t = (tx >= off) ? s[tx - off] : 0;
        __syncthreads();
        s[tx] += t;
        __syncthreads();
    }
    if (gid < NNODES) g_rowptr[gid + 1] = s[tx];
    if (tx == SCAN_B - 1) g_bsum[blockIdx.x] = s[tx];
}

__global__ void scan2_kernel() {
    __shared__ int s[128];
    int tx = threadIdx.x;
    int v = (tx < NBLK_SCAN) ? g_bsum[tx] : 0;
    s[tx] = v;
    __syncthreads();
    for (int off = 1; off < 128; off <<= 1) {
        int t = (tx >= off) ? s[tx - off] : 0;
        __syncthreads();
        s[tx] += t;
        __syncthreads();
    }
    if (tx < NBLK_SCAN) g_bsum[tx] = s[tx];
}

__global__ void scan3_kernel() {
    int gid = blockIdx.x * SCAN_B + threadIdx.x;
    if (gid < NNODES) {
        int off = blockIdx.x ? g_bsum[blockIdx.x - 1] : 0;
        int v = g_rowptr[gid + 1] + off;
        g_rowptr[gid + 1] = v;
        if (gid + 1 < NNODES) g_cursor[gid + 1] = v;
        if (gid == 0) { g_rowptr[0] = 0; g_cursor[0] = 0; }
    }
}

__global__ void scatter_kernel(const int* __restrict__ erow,
                               const int* __restrict__ ecol,
                               const float* __restrict__ eval) {
    int e = blockIdx.x * blockDim.x + threadIdx.x;
    if (e < NEDGES) {
        int r = erow[e];
        int p = atomicAdd(&g_cursor[r], 1);
        g_edge[p] = make_int2(ecol[e], __float_as_int(eval[e]));
    }
}

// ============================ fp16 conversion ============================

// X fp32 -> fp16 same layout, vec4
__global__ void conv_x_kernel(const float4* __restrict__ X,
                              uint2* __restrict__ Xh, int n4) {
    int i = blockIdx.x * blockDim.x + threadIdx.x;
    if (i >= n4) return;
    float4 v = X[i];
    Xh[i] = make_uint2(h2_bits(__floats2half2_rn(v.x, v.y)),
                       h2_bits(__floats2half2_rn(v.z, v.w)));
}

// W [K, N] fp32 -> WT [N, K] fp16
__global__ void conv_w_kernel(const float* __restrict__ W, int K, int Nn,
                              __half* __restrict__ WT) {
    int idx = blockIdx.x * blockDim.x + threadIdx.x;
    if (idx >= K * Nn) return;
    int k = idx / Nn, n = idx % Nn;
    WT[(size_t)n * K + k] = __float2half(W[idx]);
}

// ============================ fp16 tensor-core GEMM ============================
// Ch[M,Nn] = fp16( A[M,K] @ B[K,Nn] ), single-pass fp16, fp32 accumulate.
// A [M,K] fp16, B^T [Nn,K] fp16.
// Block tile 128x128, BK=32, 256 threads, 8 warps (4x2, each 32x64, B streamed).
// 3-stage cp.async pipeline, one __syncthreads per chunk, 2 CTAs/SM.

static constexpr int ST_A = 0;
static constexpr int ST_B = 8192;
static constexpr int STAGE_BYTES = 16384;
static constexpr int NSTAGES = 3;

__global__ __launch_bounds__(256, 2) void gemm_f16_kernel(
    int M, int Nn, int K,
    const __half* __restrict__ A, const __half* __restrict__ BT,
    __half* __restrict__ Ch)
{
    __shared__ char smem[NSTAGES * STAGE_BYTES];   // 48 KB static
    uint32_t sb = smem_u32(smem);

    int tid = threadIdx.x;
    int lane = tid & 31;
    int wid = tid >> 5;
    int wm = wid & 3;          // 4 x 32 rows
    int wn = wid >> 2;         // 2 x 64 cols
    int m0 = blockIdx.y * 128;
    int n0 = blockIdx.x * 128;

    // ---- staging coords: row (tid&127), 32B half (tid>>7) of the 64B row ----
    int srow = tid & 127;
    int shalf = tid >> 7;
    int ar = m0 + srow;
    size_t asrc = (size_t)((ar < M) ? ar : 0) * K + shalf * 16;   // halves
    size_t bsrc = (size_t)(n0 + srow) * K + shalf * 16;
    uint32_t d0 = sw64((uint32_t)(srow * 64 + shalf * 32));
    uint32_t d1 = sw64((uint32_t)(srow * 64 + shalf * 32 + 16));

    float acc[2][8][4];
#pragma unroll
    for (int i = 0; i < 2; i++)
#pragma unroll
        for (int j = 0; j < 8; j++)
#pragma unroll
            for (int q = 0; q < 4; q++) acc[i][j][q] = 0.f;

    const int NC = K / 32;

    auto stage = [&](int ch, int buf) {
        int k0 = ch * 32;
        uint32_t st = sb + buf * STAGE_BYTES;
        cp_async16(st + ST_A + d0, A + asrc + k0);
        cp_async16(st + ST_A + d1, A + asrc + k0 + 8);
        cp_async16(st + ST_B + d0, BT + bsrc + k0);
        cp_async16(st + ST_B + d1, BT + bsrc + k0 + 8);
    };

    auto compute = [&](int buf) {
        uint32_t st = sb + buf * STAGE_BYTES;
        // A fragments cached: [s][mt]
        uint32_t af[2][2][4];
#pragma unroll
        for (int s = 0; s < 2; s++) {
            uint32_t roff = (uint32_t)((wm * 32 + (lane & 15)) * 64
                                       + s * 32 + (lane >> 4) * 16);
#pragma unroll
            for (int mt = 0; mt < 2; mt++) {
                ldsm_x4(af[s][mt], st + ST_A + sw64(roff + (uint32_t)(mt * 16 * 64)));
            }
        }
        // B streamed per n-tile (8 tiles of n=8)
        uint32_t bro = (uint32_t)((wn * 64 + (lane & 7)) * 64 + (lane >> 3) * 16);
#pragma unroll
        for (int nt = 0; nt < 8; nt++) {
            uint32_t bf[4];
            ldsm_x4(bf, st + ST_B + sw64(bro + (uint32_t)(nt * 8 * 64)));
#pragma unroll
            for (int s = 0; s < 2; s++)
#pragma unroll
                for (int mt = 0; mt < 2; mt++)
                    mma_f16(acc[mt][nt], af[s][mt], bf[2 * s], bf[2 * s + 1]);
        }
    };

    // ---- 3-stage pipeline ----
    stage(0, 0); cp_commit();
    stage(1, 1); cp_commit();

    for (int ch = 0; ch < NC; ch++) {
        if (ch == NC - 1) cp_wait<0>(); else cp_wait<1>();
        __syncthreads();
        compute(ch % NSTAGES);
        if (ch + 2 < NC) {
            stage(ch + 2, (ch + 2) % NSTAGES);
            cp_commit();
        }
    }

    // ---- epilogue: fp32 acc -> fp16 ----
#pragma unroll
    for (int mt = 0; mt < 2; mt++) {
        int r0 = m0 + wm * 32 + mt * 16 + (lane >> 2);
        int r1 = r0 + 8;
#pragma unroll
        for (int nt = 0; nt < 8; nt++) {
            int c = n0 + wn * 64 + nt * 8 + (lane & 3) * 2;
            if (r0 < M)
                *reinterpret_cast<__half2*>(Ch + (size_t)r0 * Nn + c) =
                    __floats2half2_rn(acc[mt][nt][0], acc[mt][nt][1]);
            if (r1 < M)
                *reinterpret_cast<__half2*>(Ch + (size_t)r1 * Nn + c) =
                    __floats2half2_rn(acc[mt][nt][2], acc[mt][nt][3]);
        }
    }
}

// ============================ SpMM (fp16 gather) + bias + PReLU ============================
// Warp per row: 32 lanes x 8 fp16 features (16B) = 256 features.
// HALF_OUT=true: write fp16 (feeds GEMM2). false: write fp32 (final out).

template<bool HALF_OUT>
__global__ __launch_bounds__(256) void spmm_bias_prelu_kernel(
    const uint4* __restrict__ sup, const float* __restrict__ bias,
    const float* __restrict__ alpha, float4* __restrict__ outF,
    uint4* __restrict__ outH)
{
    int lane = threadIdx.x & 31;
    int wrp  = threadIdx.x >> 5;
    int r = blockIdx.x * 8 + wrp;
    if (r >= NNODES) return;

    int s = g_rowptr[r];
    int e = g_rowptr[r + 1];

    float acc[8];
#pragma unroll
    for (int q = 0; q < 8; q++) acc[q] = 0.f;

    int j = s;
    for (; j + 1 < e; j += 2) {
        int2 E0 = g_edge[j];
        int2 E1 = g_edge[j + 1];
        float v0 = __int_as_float(E0.y);
        float v1 = __int_as_float(E1.y);
        uint4 p0 = sup[(size_t)E0.x * 32 + lane];
        uint4 p1 = sup[(size_t)E1.x * 32 + lane];
        const uint32_t* w0 = &p0.x;
        const uint32_t* w1 = &p1.x;
#pragma unroll
        for (int q = 0; q < 4; q++) {
            float2 f0 = __half22float2(*reinterpret_cast<const __half2*>(&w0[q]));
            float2 f1 = __half22float2(*reinterpret_cast<const __half2*>(&w1[q]));
            acc[2 * q + 0] += v0 * f0.x + v1 * f1.x;
            acc[2 * q + 1] += v0 * f0.y + v1 * f1.y;
        }
    }
    if (j < e) {
        int2 E0 = g_edge[j];
        float v0 = __int_as_float(E0.y);
        uint4 p0 = sup[(size_t)E0.x * 32 + lane];
        const uint32_t* w0 = &p0.x;
#pragma unroll
        for (int q = 0; q < 4; q++) {
            float2 f0 = __half22float2(*reinterpret_cast<const __half2*>(&w0[q]));
            acc[2 * q + 0] += v0 * f0.x;
            acc[2 * q + 1] += v0 * f0.y;
        }
    }

    float a = alpha[0];
    const float4* bp = reinterpret_cast<const float4*>(bias) + lane * 2;
    float4 b0 = bp[0], b1 = bp[1];
    float o[8];
    o[0] = acc[0] + b0.x; o[1] = acc[1] + b0.y;
    o[2] = acc[2] + b0.z; o[3] = acc[3] + b0.w;
    o[4] = acc[4] + b1.x; o[5] = acc[5] + b1.y;
    o[6] = acc[6] + b1.z; o[7] = acc[7] + b1.w;
#pragma unroll
    for (int q = 0; q < 8; q++) o[q] = o[q] >= 0.f ? o[q] : a * o[q];

    if (HALF_OUT) {
        uint4 hv;
        hv.x = h2_bits(__floats2half2_rn(o[0], o[1]));
        hv.y = h2_bits(__floats2half2_rn(o[2], o[3]));
        hv.z = h2_bits(__floats2half2_rn(o[4], o[5]));
        hv.w = h2_bits(__floats2half2_rn(o[6], o[7]));
        outH[(size_t)r * 32 + lane] = hv;
    } else {
        float4* op = outF + (size_t)r * 64 + lane * 2;
        op[0] = make_float4(o[0], o[1], o[2], o[3]);
        op[1] = make_float4(o[4], o[5], o[6], o[7]);
    }
}

// ============================ launch ============================

extern "C" void kernel_launch(void* const* d_in, const int* in_sizes, int n_in,
                              void* d_out, int out_size) {
    const float* x     = (const float*)d_in[0];
    const int*   erow  = (const int*)  d_in[1];
    const int*   ecol  = (const int*)  d_in[2];
    const float* eval  = (const float*)d_in[3];
    const float* W1    = (const float*)d_in[4];
    const float* b1    = (const float*)d_in[5];
    const float* W2    = (const float*)d_in[6];
    const float* b2    = (const float*)d_in[7];
    const float* alpha = (const float*)d_in[8];
    float* out = (float*)d_out;

    __half *suph = nullptr, *xh = nullptr, *h1h = nullptr, *w1T = nullptr, *w2T = nullptr;
    cudaGetSymbolAddress((void**)&suph, g_sup_h);
    cudaGetSymbolAddress((void**)&xh, g_x_h);
    cudaGetSymbolAddress((void**)&h1h, g_h1_h);
    cudaGetSymbolAddress((void**)&w1T, g_w1T);
    cudaGetSymbolAddress((void**)&w2T, g_w2T);

    dim3 gemm_grid(NHID / 128, (NNODES + 127) / 128);   // (2, 782)
    int spmm_grid = (NNODES + 7) / 8;
    int n4 = NNODES * NFEAT / 4;

    conv_w_kernel<<<(NFEAT * NHID + 255) / 256, 256>>>(W1, NFEAT, NHID, w1T);           // 0
    conv_w_kernel<<<(NHID * NHID + 255) / 256, 256>>>(W2, NHID, NHID, w2T);             // 1
    conv_x_kernel<<<(n4 + 255) / 256, 256>>>((const float4*)x, (uint2*)xh, n4);         // 2
    gemm_f16_kernel<<<gemm_grid, 256>>>(NNODES, NHID, NFEAT, xh, w1T, suph);            // 3 (captured)
    zero_deg_kernel<<<(NNODES + 255) / 256, 256>>>();                                   // 4
    count_deg_kernel<<<NEDGES / 256, 256>>>(erow);                                      // 5
    scan1_kernel<<<NBLK_SCAN, SCAN_B>>>();                                              // 6
    scan2_kernel<<<1, 128>>>();                                                         // 7
    scan3_kernel<<<NBLK_SCAN, SCAN_B>>>();                                              // 8
    scatter_kernel<<<NEDGES / 256, 256>>>(erow, ecol, eval);                            // 9
    spmm_bias_prelu_kernel<true><<<spmm_grid, 256>>>(
        (const uint4*)suph, b1, alpha, nullptr, (uint4*)h1h);                           // 10
    gemm_f16_kernel<<<gemm_grid, 256>>>(NNODES, NHID, NHID, h1h, w2T, suph);            // 11
    spmm_bias_prelu_kernel<false><<<spmm_grid, 256>>>(
        (const uint4*)suph, b2, alpha, (float4*)out, nullptr);                          // 12
}

// round 17
// speedup vs baseline: 1.4385x; 1.0056x over previous
#include <cuda_runtime.h>
#include <cuda_fp16.h>
#include <cstdint>

static constexpr int NNODES = 100000;
static constexpr int NEDGES = 3200000;
static constexpr int NFEAT  = 512;
static constexpr int NHID   = 256;
static constexpr int SCAN_B = 1024;
static constexpr int NBLK_SCAN = (NNODES + SCAN_B - 1) / SCAN_B;  // 98

// ---- static device scratch (allocation-free per harness rules) ----
__device__ __half g_sup_h[NNODES * NHID];   // GEMM out fp16 (SpMM gathers)
__device__ __half g_x_h[NNODES * NFEAT];    // x in fp16
__device__ __half g_h1_h[NNODES * NHID];    // layer-1 out fp16 (feeds GEMM2)
__device__ __half g_w1T[NHID * NFEAT];      // W1^T fp16 [N,K]
__device__ __half g_w2T[NHID * NHID];       // W2^T fp16 [N,K]
__device__ int    g_rowptr[NNODES + 1];
__device__ int    g_cursor[NNODES];
__device__ int    g_deg[NNODES];
__device__ int    g_bsum[128];
__device__ int2   g_edge[NEDGES];           // packed {col, val_bits}

// ============================ helpers ============================

__device__ __forceinline__ uint32_t smem_u32(const void* p) {
    uint32_t a;
    asm("{ .reg .u64 t; cvta.to.shared.u64 t, %1; cvt.u32.u64 %0, t; }"
        : "=r"(a) : "l"(p));
    return a;
}

__device__ __forceinline__ uint32_t h2_bits(__half2 h) {
    return *reinterpret_cast<uint32_t*>(&h);
}

__device__ __forceinline__ void ldsm_x4(uint32_t* r, uint32_t addr) {
    asm volatile("ldmatrix.sync.aligned.m8n8.x4.shared.b16 {%0,%1,%2,%3}, [%4];"
        : "=r"(r[0]), "=r"(r[1]), "=r"(r[2]), "=r"(r[3]) : "r"(addr));
}

__device__ __forceinline__ void mma_f16(float* c, const uint32_t* a,
                                        uint32_t b0, uint32_t b1) {
    asm volatile(
        "mma.sync.aligned.m16n8k16.row.col.f32.f16.f16.f32 "
        "{%0,%1,%2,%3}, {%4,%5,%6,%7}, {%8,%9}, {%0,%1,%2,%3};"
        : "+f"(c[0]), "+f"(c[1]), "+f"(c[2]), "+f"(c[3])
        : "r"(a[0]), "r"(a[1]), "r"(a[2]), "r"(a[3]), "r"(b0), "r"(b1));
}

__device__ __forceinline__ void cp_async16(uint32_t smem_addr, const void* gmem) {
    asm volatile("cp.async.ca.shared.global [%0], [%1], 16;"
        :: "r"(smem_addr), "l"(gmem));
}
__device__ __forceinline__ void cp_commit() {
    asm volatile("cp.async.commit_group;");
}
template<int N>
__device__ __forceinline__ void cp_wait() {
    asm volatile("cp.async.wait_group %0;" :: "n"(N));
}

// ============================ CSR construction ============================

__global__ void zero_deg_kernel() {
    int i = blockIdx.x * blockDim.x + threadIdx.x;
    if (i < NNODES) g_deg[i] = 0;
}

__global__ void count_deg_kernel(const int* __restrict__ erow) {
    int e = blockIdx.x * blockDim.x + threadIdx.x;
    if (e < NEDGES) atomicAdd(&g_deg[erow[e]], 1);
}

__global__ void scan1_kernel() {
    __shared__ int s[SCAN_B];
    int tx = threadIdx.x;
    int gid = blockIdx.x * SCAN_B + tx;
    int v = (gid < NNODES) ? g_deg[gid] : 0;
    s[tx] = v;
    __syncthreads();
    for (int off = 1; off < SCAN_B; off <<= 1) {
        int t = (tx >= off) ? s[tx - off] : 0;
        __syncthreads();
        s[tx] += t;
        __syncthreads();
    }
    if (gid < NNODES) g_rowptr[gid + 1] = s[tx];
    if (tx == SCAN_B - 1) g_bsum[blockIdx.x] = s[tx];
}

__global__ void scan2_kernel() {
    __shared__ int s[128];
    int tx = threadIdx.x;
    int v = (tx < NBLK_SCAN) ? g_bsum[tx] : 0;
    s[tx] = v;
    __syncthreads();
    for (int off = 1; off < 128; off <<= 1) {
        int t = (tx >= off) ? s[tx - off] : 0;
        __syncthreads();
        s[tx] += t;
        __syncthreads();
    }
    if (tx < NBLK_SCAN) g_bsum[tx] = s[tx];
}

__global__ void scan3_kernel() {
    int gid = blockIdx.x * SCAN_B + threadIdx.x;
    if (gid < NNODES) {
        int off = blockIdx.x ? g_bsum[blockIdx.x - 1] : 0;
        int v = g_rowptr[gid + 1] + off;
        g_rowptr[gid + 1] = v;
        if (gid + 1 < NNODES) g_cursor[gid + 1] = v;
        if (gid == 0) { g_rowptr[0] = 0; g_cursor[0] = 0; }
    }
}

__global__ void scatter_kernel(const int* __restrict__ erow,
                               const int* __restrict__ ecol,
                               const float* __restrict__ eval) {
    int e = blockIdx.x * blockDim.x + threadIdx.x;
    if (e < NEDGES) {
        int r = erow[e];
        int p = atomicAdd(&g_cursor[r], 1);
        g_edge[p] = make_int2(ecol[e], __float_as_int(eval[e]));
    }
}

// ============================ fp16 conversion ============================

// X fp32 -> fp16 same layout, vec4
__global__ void conv_x_kernel(const float4* __restrict__ X,
                              uint2* __restrict__ Xh, int n4) {
    int i = blockIdx.x * blockDim.x + threadIdx.x;
    if (i >= n4) return;
    float4 v = X[i];
    Xh[i] = make_uint2(h2_bits(__floats2half2_rn(v.x, v.y)),
                       h2_bits(__floats2half2_rn(v.z, v.w)));
}

// W [K, N] fp32 -> WT [N, K] fp16
__global__ void conv_w_kernel(const float* __restrict__ W, int K, int Nn,
                              __half* __restrict__ WT) {
    int idx = blockIdx.x * blockDim.x + threadIdx.x;
    if (idx >= K * Nn) return;
    int k = idx / Nn, n = idx % Nn;
    WT[(size_t)n * K + k] = __float2half(W[idx]);
}

// ============================ fp16 tensor-core GEMM ============================
// Ch[M,Nn] = fp16( A[M,K] @ B[K,Nn] ), single-pass fp16, fp32 accumulate.
// A [M,K] fp16, B^T [Nn,K] fp16.
// Block tile 128x128, BK=32, 256 threads, 8 warps (4x2, each 32x64, B streamed).
// LINE-DENSE ldsm layout: each 8x8 ldsm matrix = one 128B line:
//   offset(r, kf) = ((r>>3)*4 + kf)*128 + (r&7)*16,  kf in 0..3 (BK=32).
// -> every ldsm.x4 = exactly 4 L1 wavefronts, no swizzle needed.
// 3-stage cp.async pipeline, one __syncthreads per chunk, 2 CTAs/SM.

static constexpr int ST_A = 0;
static constexpr int ST_B = 8192;
static constexpr int STAGE_BYTES = 16384;
static constexpr int NSTAGES = 3;

__global__ __launch_bounds__(256, 2) void gemm_f16_kernel(
    int M, int Nn, int K,
    const __half* __restrict__ A, const __half* __restrict__ BT,
    __half* __restrict__ Ch)
{
    __shared__ char smem[NSTAGES * STAGE_BYTES];   // 48 KB static
    uint32_t sb = smem_u32(smem);

    int tid = threadIdx.x;
    int lane = tid & 31;
    int wid = tid >> 5;
    int wm = wid & 3;          // 4 x 32 rows
    int wn = wid >> 2;         // 2 x 64 cols
    int m0 = blockIdx.y * 128;
    int n0 = blockIdx.x * 128;

    // ---- staging coords: row (tid&127), kf-pair (tid>>7) ----
    int srow = tid & 127;
    int shalf = tid >> 7;              // 0 -> kf {0,1}, 1 -> kf {2,3}
    int ar = m0 + srow;
    size_t asrc = (size_t)((ar < M) ? ar : 0) * K + shalf * 16;   // halves
    size_t bsrc = (size_t)(n0 + srow) * K + shalf * 16;
    // line-dense frag destinations
    uint32_t fd0 = (uint32_t)(((srow >> 3) * 4 + 2 * shalf) * 128 + (srow & 7) * 16);
    uint32_t fd1 = fd0 + 128;

    // per-lane ldsm address components
    int lg = lane >> 3;                // matrix group 0..3
    int lr = lane & 7;                 // row within 8x8

    float acc[2][8][4];
#pragma unroll
    for (int i = 0; i < 2; i++)
#pragma unroll
        for (int j = 0; j < 8; j++)
#pragma unroll
            for (int q = 0; q < 4; q++) acc[i][j][q] = 0.f;

    const int NC = K / 32;

    auto stage = [&](int ch, int buf) {
        int k0 = ch * 32;
        uint32_t st = sb + buf * STAGE_BYTES;
        cp_async16(st + ST_A + fd0, A + asrc + k0);
        cp_async16(st + ST_A + fd1, A + asrc + k0 + 8);
        cp_async16(st + ST_B + fd0, BT + bsrc + k0);
        cp_async16(st + ST_B + fd1, BT + bsrc + k0 + 8);
    };

    auto compute = [&](int buf) {
        uint32_t st = sb + buf * STAGE_BYTES;
        // A fragments cached: [s][mt]; matrix g: octet +(g&1), kf 2s+(g>>1)
        uint32_t af[2][2][4];
#pragma unroll
        for (int s = 0; s < 2; s++) {
#pragma unroll
            for (int mt = 0; mt < 2; mt++) {
                int boct = wm * 4 + mt * 2;
                uint32_t aaddr = st + ST_A +
                    (uint32_t)(((boct + (lg & 1)) * 4 + (2 * s + (lg >> 1))) * 128
                               + lr * 16);
                ldsm_x4(af[s][mt], aaddr);
            }
        }
        // B streamed per n-tile: x4 loads 4 kfrags of one n-octet
#pragma unroll
        for (int nt = 0; nt < 8; nt++) {
            uint32_t baddr = st + ST_B +
                (uint32_t)(((wn * 8 + nt) * 4 + lg) * 128 + lr * 16);
            uint32_t bf[4];
            ldsm_x4(bf, baddr);
#pragma unroll
            for (int s = 0; s < 2; s++)
#pragma unroll
                for (int mt = 0; mt < 2; mt++)
                    mma_f16(acc[mt][nt], af[s][mt], bf[2 * s], bf[2 * s + 1]);
        }
    };

    // ---- 3-stage pipeline ----
    stage(0, 0); cp_commit();
    stage(1, 1); cp_commit();

    for (int ch = 0; ch < NC; ch++) {
        if (ch == NC - 1) cp_wait<0>(); else cp_wait<1>();
        __syncthreads();
        compute(ch % NSTAGES);
        if (ch + 2 < NC) {
            stage(ch + 2, (ch + 2) % NSTAGES);
            cp_commit();
        }
    }

    // ---- epilogue: fp32 acc -> fp16 ----
#pragma unroll
    for (int mt = 0; mt < 2; mt++) {
        int r0 = m0 + wm * 32 + mt * 16 + (lane >> 2);
        int r1 = r0 + 8;
#pragma unroll
        for (int nt = 0; nt < 8; nt++) {
            int c = n0 + wn * 64 + nt * 8 + (lane & 3) * 2;
            if (r0 < M)
                *reinterpret_cast<__half2*>(Ch + (size_t)r0 * Nn + c) =
                    __floats2half2_rn(acc[mt][nt][0], acc[mt][nt][1]);
            if (r1 < M)
                *reinterpret_cast<__half2*>(Ch + (size_t)r1 * Nn + c) =
                    __floats2half2_rn(acc[mt][nt][2], acc[mt][nt][3]);
        }
    }
}

// ============================ SpMM (fp16 gather) + bias + PReLU ============================
// Warp per row: 32 lanes x 8 fp16 features (16B) = 256 features.
// HALF_OUT=true: write fp16 (feeds GEMM2). false: write fp32 (final out).

template<bool HALF_OUT>
__global__ __launch_bounds__(256) void spmm_bias_prelu_kernel(
    const uint4* __restrict__ sup, const float* __restrict__ bias,
    const float* __restrict__ alpha, float4* __restrict__ outF,
    uint4* __restrict__ outH)
{
    int lane = threadIdx.x & 31;
    int wrp  = threadIdx.x >> 5;
    int r = blockIdx.x * 8 + wrp;
    if (r >= NNODES) return;

    int s = g_rowptr[r];
    int e = g_rowptr[r + 1];

    float acc[8];
#pragma unroll
    for (int q = 0; q < 8; q++) acc[q] = 0.f;

    int j = s;
    for (; j + 1 < e; j += 2) {
        int2 E0 = g_edge[j];
        int2 E1 = g_edge[j + 1];
        float v0 = __int_as_float(E0.y);
        float v1 = __int_as_float(E1.y);
        uint4 p0 = sup[(size_t)E0.x * 32 + lane];
        uint4 p1 = sup[(size_t)E1.x * 32 + lane];
        const uint32_t* w0 = &p0.x;
        const uint32_t* w1 = &p1.x;
#pragma unroll
        for (int q = 0; q < 4; q++) {
            float2 f0 = __half22float2(*reinterpret_cast<const __half2*>(&w0[q]));
            float2 f1 = __half22float2(*reinterpret_cast<const __half2*>(&w1[q]));
            acc[2 * q + 0] += v0 * f0.x + v1 * f1.x;
            acc[2 * q + 1] += v0 * f0.y + v1 * f1.y;
        }
    }
    if (j < e) {
        int2 E0 = g_edge[j];
        float v0 = __int_as_float(E0.y);
        uint4 p0 = sup[(size_t)E0.x * 32 + lane];
        const uint32_t* w0 = &p0.x;
#pragma unroll
        for (int q = 0; q < 4; q++) {
            float2 f0 = __half22float2(*reinterpret_cast<const __half2*>(&w0[q]));
            acc[2 * q + 0] += v0 * f0.x;
            acc[2 * q + 1] += v0 * f0.y;
        }
    }

    float a = alpha[0];
    const float4* bp = reinterpret_cast<const float4*>(bias) + lane * 2;
    float4 b0 = bp[0], b1 = bp[1];
    float o[8];
    o[0] = acc[0] + b0.x; o[1] = acc[1] + b0.y;
    o[2] = acc[2] + b0.z; o[3] = acc[3] + b0.w;
    o[4] = acc[4] + b1.x; o[5] = acc[5] + b1.y;
    o[6] = acc[6] + b1.z; o[7] = acc[7] + b1.w;
#pragma unroll
    for (int q = 0; q < 8; q++) o[q] = o[q] >= 0.f ? o[q] : a * o[q];

    if (HALF_OUT) {
        uint4 hv;
        hv.x = h2_bits(__floats2half2_rn(o[0], o[1]));
        hv.y = h2_bits(__floats2half2_rn(o[2], o[3]));
        hv.z = h2_bits(__floats2half2_rn(o[4], o[5]));
        hv.w = h2_bits(__floats2half2_rn(o[6], o[7]));
        outH[(size_t)r * 32 + lane] = hv;
    } else {
        float4* op = outF + (size_t)r * 64 + lane * 2;
        op[0] = make_float4(o[0], o[1], o[2], o[3]);
        op[1] = make_float4(o[4], o[5], o[6], o[7]);
    }
}

// ============================ launch ============================

extern "C" void kernel_launch(void* const* d_in, const int* in_sizes, int n_in,
                              void* d_out, int out_size) {
    const float* x     = (const float*)d_in[0];
    const int*   erow  = (const int*)  d_in[1];
    const int*   ecol  = (const int*)  d_in[2];
    const float* eval  = (const float*)d_in[3];
    const float* W1    = (const float*)d_in[4];
    const float* b1    = (const float*)d_in[5];
    const float* W2    = (const float*)d_in[6];
    const float* b2    = (const float*)d_in[7];
    const float* alpha = (const float*)d_in[8];
    float* out = (float*)d_out;

    __half *suph = nullptr, *xh = nullptr, *h1h = nullptr, *w1T = nullptr, *w2T = nullptr;
    cudaGetSymbolAddress((void**)&suph, g_sup_h);
    cudaGetSymbolAddress((void**)&xh, g_x_h);
    cudaGetSymbolAddress((void**)&h1h, g_h1_h);
    cudaGetSymbolAddress((void**)&w1T, g_w1T);
    cudaGetSymbolAddress((void**)&w2T, g_w2T);

    dim3 gemm_grid(NHID / 128, (NNODES + 127) / 128);   // (2, 782)
    int spmm_grid = (NNODES + 7) / 8;
    int n4 = NNODES * NFEAT / 4;

    conv_w_kernel<<<(NFEAT * NHID + 255) / 256, 256>>>(W1, NFEAT, NHID, w1T);           // 0
    conv_w_kernel<<<(NHID * NHID + 255) / 256, 256>>>(W2, NHID, NHID, w2T);             // 1
    conv_x_kernel<<<(n4 + 255) / 256, 256>>>((const float4*)x, (uint2*)xh, n4);         // 2
    gemm_f16_kernel<<<gemm_grid, 256>>>(NNODES, NHID, NFEAT, xh, w1T, suph);            // 3 (captured)
    zero_deg_kernel<<<(NNODES + 255) / 256, 256>>>();                                   // 4
    count_deg_kernel<<<NEDGES / 256, 256>>>(erow);                                      // 5
    scan1_kernel<<<NBLK_SCAN, SCAN_B>>>();                                              // 6
    scan2_kernel<<<1, 128>>>();                                                         // 7
    scan3_kernel<<<NBLK_SCAN, SCAN_B>>>();                                              // 8
    scatter_kernel<<<NEDGES / 256, 256>>>(erow, ecol, eval);                            // 9
    spmm_bias_prelu_kernel<true><<<spmm_grid, 256>>>(
        (const uint4*)suph, b1, alpha, nullptr, (uint4*)h1h);                           // 10
    gemm_f16_kernel<<<gemm_grid, 256>>>(NNODES, NHID, NHID, h1h, w2T, suph);            // 11
    spmm_bias_prelu_kernel<false><<<spmm_grid, 256>>>(
        (const uint4*)suph, b2, alpha, (float4*)out, nullptr);                          // 12
}